// round 4
// baseline (speedup 1.0000x reference)
#include <cuda_runtime.h>
#include <cstddef>

#define NV 25000
#define NE 400000
#define H  192
#define BM 64
#define BK 16

// ---------------- scratch (static device globals; no runtime allocation) ---------
__device__ float g_Y[(size_t)NV * H];   // aggregation output
__device__ float g_X[(size_t)NV * H];   // intra-block activation
__device__ float g_F[(size_t)NV * H];   // feats (residual stream)
__device__ int   g_rowptr[NV + 1];
__device__ int   g_cnt[NV];
__device__ int   g_fill[NV];
__device__ int   g_ssrc[NE];
__device__ float g_sw[NE];

// ---------------- CSR build ------------------------------------------------------
__global__ void k_zero2(int* a, int* b, int n) {
    int i = blockIdx.x * blockDim.x + threadIdx.x;
    if (i < n) { a[i] = 0; b[i] = 0; }
}

__global__ void k_hist(const int* __restrict__ dst, int* cnt, int E) {
    int i = blockIdx.x * blockDim.x + threadIdx.x;
    if (i < E) atomicAdd(&cnt[dst[i]], 1);
}

// single-block exclusive scan over n<=NV elements
__global__ void k_scan(const int* __restrict__ cnt, int* __restrict__ rowptr, int n) {
    __shared__ int sh[1024];
    __shared__ int s_carry;
    if (threadIdx.x == 0) s_carry = 0;
    __syncthreads();
    for (int base = 0; base < n; base += 1024) {
        int i = base + threadIdx.x;
        int v = (i < n) ? cnt[i] : 0;
        int x = v;
        sh[threadIdx.x] = x;
        __syncthreads();
        for (int off = 1; off < 1024; off <<= 1) {
            int t = (threadIdx.x >= off) ? sh[threadIdx.x - off] : 0;
            __syncthreads();
            x += t;
            sh[threadIdx.x] = x;
            __syncthreads();
        }
        int carry = s_carry;
        if (i < n) rowptr[i] = carry + x - v;
        __syncthreads();
        if (threadIdx.x == 1023) s_carry = carry + sh[1023];
        __syncthreads();
    }
    if (threadIdx.x == 0) rowptr[n] = s_carry;
}

__global__ void k_scatter(const int* __restrict__ src, const int* __restrict__ dst,
                          const float* __restrict__ w, const int* __restrict__ rowptr,
                          int* fill, int* ssrc, float* sw, int E) {
    int i = blockIdx.x * blockDim.x + threadIdx.x;
    if (i < E) {
        int d = dst[i];
        int pos = rowptr[d] + atomicAdd(&fill[d], 1);
        ssrc[pos] = src[i];
        sw[pos]   = w[i];
    }
}

// ---------------- sparse aggregation: Y[d] = sum_e w_e * X[src_e] ----------------
// one warp per destination vertex; 6 accumulators (192 = 6*32)
__global__ __launch_bounds__(256) void k_agg(const float* __restrict__ X,
                                             float* __restrict__ Y,
                                             const int* __restrict__ rowptr,
                                             const int* __restrict__ ssrc,
                                             const float* __restrict__ sw, int M) {
    int warp = (blockIdx.x * blockDim.x + threadIdx.x) >> 5;
    int lane = threadIdx.x & 31;
    if (warp >= M) return;
    int beg = rowptr[warp], end = rowptr[warp + 1];
    float a0 = 0.f, a1 = 0.f, a2 = 0.f, a3 = 0.f, a4 = 0.f, a5 = 0.f;
#pragma unroll 2
    for (int e = beg; e < end; e++) {
        int   s  = __ldg(ssrc + e);
        float wt = __ldg(sw + e);
        const float* r = X + (size_t)s * H;
        a0 += wt * __ldg(r + lane);
        a1 += wt * __ldg(r + lane + 32);
        a2 += wt * __ldg(r + lane + 64);
        a3 += wt * __ldg(r + lane + 96);
        a4 += wt * __ldg(r + lane + 128);
        a5 += wt * __ldg(r + lane + 160);
    }
    float* o = Y + (size_t)warp * H;
    o[lane]       = a0;
    o[lane + 32]  = a1;
    o[lane + 64]  = a2;
    o[lane + 96]  = a3;
    o[lane + 128] = a4;
    o[lane + 160] = a5;
}

// ---------------- fused GEMM + epilogue ------------------------------------------
// C = A[M,192] @ W[192,192];  out = relu(C + bias)  (mode 0)
//                             out = (res + relu(C + bias)) * 0.5  (mode 1)
// block: 64 rows x 192 cols, 256 threads, 4x12 micro-tile, double-buffered smem.
__global__ __launch_bounds__(256) void k_gemm(const float* __restrict__ A,
                                              const float* __restrict__ Wm,
                                              const float* __restrict__ bias,
                                              const float* __restrict__ res,
                                              float* __restrict__ out,
                                              int M, int mode) {
    __shared__ float As[2][BK][BM + 4];   // k-major (transposed), padded
    __shared__ float Bs[2][BK][H];

    int tid = threadIdx.x;
    int tx  = tid & 15;      // col group: cols tx*12 .. tx*12+11
    int ty  = tid >> 4;      // row group: rows ty*4 .. ty*4+3
    int m0  = blockIdx.x * BM;

    // loader mapping
    int lr = tid >> 2;            // A row within tile (0..63)
    int lk = (tid & 3) * 4;       // A k offset (0,4,8,12)

    float acc[4][12];
#pragma unroll
    for (int i = 0; i < 4; i++)
#pragma unroll
        for (int j = 0; j < 12; j++) acc[i][j] = 0.f;

    float4 areg;
    float4 breg[3];

    // prologue: tile 0
    {
        int gr = m0 + lr;
        areg = (gr < M) ? *(const float4*)(A + (size_t)gr * H + lk)
                        : make_float4(0.f, 0.f, 0.f, 0.f);
#pragma unroll
        for (int i = 0; i < 3; i++) {
            int idx = tid + 256 * i;
            int r = idx / 48, c4 = (idx % 48) * 4;
            breg[i] = *(const float4*)(Wm + (size_t)r * H + c4);
        }
        As[0][lk + 0][lr] = areg.x;
        As[0][lk + 1][lr] = areg.y;
        As[0][lk + 2][lr] = areg.z;
        As[0][lk + 3][lr] = areg.w;
#pragma unroll
        for (int i = 0; i < 3; i++) {
            int idx = tid + 256 * i;
            int r = idx / 48, c4 = (idx % 48) * 4;
            *(float4*)&Bs[0][r][c4] = breg[i];
        }
    }

    const int KIT = H / BK;   // 12
    for (int it = 0; it < KIT; it++) {
        __syncthreads();
        bool nb = (it + 1 < KIT);
        if (nb) {
            int k0 = (it + 1) * BK;
            int gr = m0 + lr;
            areg = (gr < M) ? *(const float4*)(A + (size_t)gr * H + k0 + lk)
                            : make_float4(0.f, 0.f, 0.f, 0.f);
#pragma unroll
            for (int i = 0; i < 3; i++) {
                int idx = tid + 256 * i;
                int r = idx / 48, c4 = (idx % 48) * 4;
                breg[i] = *(const float4*)(Wm + (size_t)(k0 + r) * H + c4);
            }
        }
        int cur = it & 1;
#pragma unroll
        for (int k = 0; k < BK; k++) {
            float4 a  = *(const float4*)&As[cur][k][ty * 4];
            float4 b0 = *(const float4*)&Bs[cur][k][tx * 12];
            float4 b1 = *(const float4*)&Bs[cur][k][tx * 12 + 4];
            float4 b2 = *(const float4*)&Bs[cur][k][tx * 12 + 8];
            float av[4] = {a.x, a.y, a.z, a.w};
            float bv[12] = {b0.x, b0.y, b0.z, b0.w,
                            b1.x, b1.y, b1.z, b1.w,
                            b2.x, b2.y, b2.z, b2.w};
#pragma unroll
            for (int i = 0; i < 4; i++)
#pragma unroll
                for (int j = 0; j < 12; j++)
                    acc[i][j] += av[i] * bv[j];
        }
        if (nb) {
            int nxt = cur ^ 1;
            As[nxt][lk + 0][lr] = areg.x;
            As[nxt][lk + 1][lr] = areg.y;
            As[nxt][lk + 2][lr] = areg.z;
            As[nxt][lk + 3][lr] = areg.w;
#pragma unroll
            for (int i = 0; i < 3; i++) {
                int idx = tid + 256 * i;
                int r = idx / 48, c4 = (idx % 48) * 4;
                *(float4*)&Bs[nxt][r][c4] = breg[i];
            }
        }
    }

    // epilogue
    float bj[12];
#pragma unroll
    for (int j = 0; j < 12; j++) bj[j] = __ldg(bias + tx * 12 + j);

#pragma unroll
    for (int i = 0; i < 4; i++) {
        int m = m0 + ty * 4 + i;
        if (m < M) {
            float* orow = out + (size_t)m * H + tx * 12;
            const float* rrow = res + (size_t)m * H + tx * 12;   // only read if mode==1
#pragma unroll
            for (int q = 0; q < 3; q++) {
                float4 v;
                float v0 = fmaxf(acc[i][q * 4 + 0] + bj[q * 4 + 0], 0.f);
                float v1 = fmaxf(acc[i][q * 4 + 1] + bj[q * 4 + 1], 0.f);
                float v2 = fmaxf(acc[i][q * 4 + 2] + bj[q * 4 + 2], 0.f);
                float v3 = fmaxf(acc[i][q * 4 + 3] + bj[q * 4 + 3], 0.f);
                if (mode == 1) {
                    float4 r4 = *(const float4*)(rrow + q * 4);
                    v0 = (r4.x + v0) * 0.5f;
                    v1 = (r4.y + v1) * 0.5f;
                    v2 = (r4.z + v2) * 0.5f;
                    v3 = (r4.w + v3) * 0.5f;
                }
                v.x = v0; v.y = v1; v.z = v2; v.w = v3;
                *(float4*)(orow + q * 4) = v;
            }
        }
    }
}

// ---------------- output head: coords = Y @ W_out + b_out (192 -> 3) -------------
__global__ __launch_bounds__(256) void k_head(const float* __restrict__ Y,
                                              const float* __restrict__ Wout,
                                              const float* __restrict__ bout,
                                              float* __restrict__ out, int M) {
    int warp = (blockIdx.x * blockDim.x + threadIdx.x) >> 5;
    int lane = threadIdx.x & 31;
    if (warp >= M) return;
    const float* y = Y + (size_t)warp * H;
    float a0 = 0.f, a1 = 0.f, a2 = 0.f;
#pragma unroll
    for (int k0 = 0; k0 < H; k0 += 32) {
        float v = __ldg(y + k0 + lane);
        const float* wr = Wout + (size_t)(k0 + lane) * 3;
        a0 += v * __ldg(wr + 0);
        a1 += v * __ldg(wr + 1);
        a2 += v * __ldg(wr + 2);
    }
#pragma unroll
    for (int off = 16; off; off >>= 1) {
        a0 += __shfl_down_sync(0xffffffffu, a0, off);
        a1 += __shfl_down_sync(0xffffffffu, a1, off);
        a2 += __shfl_down_sync(0xffffffffu, a2, off);
    }
    if (lane == 0) {
        out[(size_t)warp * 3 + 0] = a0 + __ldg(bout + 0);
        out[(size_t)warp * 3 + 1] = a1 + __ldg(bout + 1);
        out[(size_t)warp * 3 + 2] = a2 + __ldg(bout + 2);
    }
}

__global__ void k_copy4(const float* __restrict__ src, float* __restrict__ dst, int n4) {
    int i = blockIdx.x * blockDim.x + threadIdx.x;
    if (i < n4) ((float4*)dst)[i] = ((const float4*)src)[i];
}

// ---------------- launch ---------------------------------------------------------
extern "C" void kernel_launch(void* const* d_in, const int* in_sizes, int n_in,
                              void* d_out, int out_size) {
    const float* features = (const float*)d_in[0];
    const int*   esrc     = (const int*)d_in[1];
    const int*   edst     = (const int*)d_in[2];
    const float* ew       = (const float*)d_in[3];
    const float* Ws       = (const float*)d_in[4];
    const float* bs       = (const float*)d_in[5];
    const float* Wout     = (const float*)d_in[6];
    const float* bout     = (const float*)d_in[7];
    float* out = (float*)d_out;

    int M = in_sizes[0] / H;   // 25000
    int E = in_sizes[1];       // 400000

    float *Y, *X, *F, *sw;
    int *rp, *cnt, *fill, *ssrc;
    cudaGetSymbolAddress((void**)&Y, g_Y);
    cudaGetSymbolAddress((void**)&X, g_X);
    cudaGetSymbolAddress((void**)&F, g_F);
    cudaGetSymbolAddress((void**)&sw, g_sw);
    cudaGetSymbolAddress((void**)&rp, g_rowptr);
    cudaGetSymbolAddress((void**)&cnt, g_cnt);
    cudaGetSymbolAddress((void**)&fill, g_fill);
    cudaGetSymbolAddress((void**)&ssrc, g_ssrc);

    // ---- CSR build (by destination) ----
    k_zero2<<<(M + 255) / 256, 256>>>(cnt, fill, M);
    k_hist<<<(E + 255) / 256, 256>>>(edst, cnt, E);
    k_scan<<<1, 1024>>>(cnt, rp, M);
    k_scatter<<<(E + 255) / 256, 256>>>(esrc, edst, ew, rp, fill, ssrc, sw, E);

    int aggGrid  = (M * 32 + 255) / 256;
    int gemmGrid = (M + BM - 1) / BM;

    // layer 0: x = relu(gcn(features))
    k_agg<<<aggGrid, 256>>>(features, Y, rp, ssrc, sw, M);
    k_gemm<<<gemmGrid, 256>>>(Y, Ws, bs, features /*unused*/, X, M, 0);
    // layer 1: feats = (features + relu(gcn(x))) / 2
    k_agg<<<aggGrid, 256>>>(X, Y, rp, ssrc, sw, M);
    k_gemm<<<gemmGrid, 256>>>(Y, Ws + (size_t)1 * H * H, bs + 1 * H, features, F, M, 1);

    // blocks: layers (2,3) (4,5) (6,7) (8,9) (10,11)
    for (int l = 2; l < 12; l += 2) {
        k_agg<<<aggGrid, 256>>>(F, Y, rp, ssrc, sw, M);
        k_gemm<<<gemmGrid, 256>>>(Y, Ws + (size_t)l * H * H, bs + (size_t)l * H, F /*unused*/, X, M, 0);
        k_agg<<<aggGrid, 256>>>(X, Y, rp, ssrc, sw, M);
        k_gemm<<<gemmGrid, 256>>>(Y, Ws + (size_t)(l + 1) * H * H, bs + (size_t)(l + 1) * H, F, F, M, 1);
    }

    // gc13: feats = (feats + relu(gcn(feats))) / 2
    k_agg<<<aggGrid, 256>>>(F, Y, rp, ssrc, sw, M);
    k_gemm<<<gemmGrid, 256>>>(Y, Ws + (size_t)12 * H * H, bs + (size_t)12 * H, F, F, M, 1);

    // head: coords = gcn(feats) with W_out/b_out (no relu)
    k_agg<<<aggGrid, 256>>>(F, Y, rp, ssrc, sw, M);
    k_head<<<(M * 32 + 255) / 256, 256>>>(Y, Wout, bout, out, M);

    // second output: feats, appended after coords
    if (out_size >= M * 3 + M * H) {
        k_copy4<<<((M * H) / 4 + 255) / 256, 256>>>(F, out + (size_t)M * 3, (M * H) / 4);
    }
}

// round 6
// speedup vs baseline: 1.5091x; 1.5091x over previous
#include <cuda_runtime.h>
#include <cstddef>

#define NV 25000
#define NE 400000
#define H  192
#define BM 64

// ---------------- scratch (static device globals; no runtime allocation) ---------
__device__ float g_Y[(size_t)NV * H];   // aggregation output
__device__ float g_X[(size_t)NV * H];   // intra-block activation
__device__ float g_F[(size_t)NV * H];   // feats (residual stream)
__device__ int   g_rowptr[NV + 1];
__device__ int   g_cnt[NV];
__device__ int   g_fill[NV];
__device__ int   g_ssrc[NE];
__device__ float g_sw[NE];

// ---------------- CSR build ------------------------------------------------------
__global__ void k_zero2(int* a, int* b, int n) {
    int i = blockIdx.x * blockDim.x + threadIdx.x;
    if (i < n) { a[i] = 0; b[i] = 0; }
}

__global__ void k_hist(const int* __restrict__ dst, int* cnt, int E) {
    int i = blockIdx.x * blockDim.x + threadIdx.x;
    if (i < E) atomicAdd(&cnt[dst[i]], 1);
}

// single-block exclusive scan over n<=NV elements
__global__ void k_scan(const int* __restrict__ cnt, int* __restrict__ rowptr, int n) {
    __shared__ int sh[1024];
    __shared__ int s_carry;
    if (threadIdx.x == 0) s_carry = 0;
    __syncthreads();
    for (int base = 0; base < n; base += 1024) {
        int i = base + threadIdx.x;
        int v = (i < n) ? cnt[i] : 0;
        int x = v;
        sh[threadIdx.x] = x;
        __syncthreads();
        for (int off = 1; off < 1024; off <<= 1) {
            int t = (threadIdx.x >= off) ? sh[threadIdx.x - off] : 0;
            __syncthreads();
            x += t;
            sh[threadIdx.x] = x;
            __syncthreads();
        }
        int carry = s_carry;
        if (i < n) rowptr[i] = carry + x - v;
        __syncthreads();
        if (threadIdx.x == 1023) s_carry = carry + sh[1023];
        __syncthreads();
    }
    if (threadIdx.x == 0) rowptr[n] = s_carry;
}

__global__ void k_scatter(const int* __restrict__ src, const int* __restrict__ dst,
                          const float* __restrict__ w, const int* __restrict__ rowptr,
                          int* fill, int* ssrc, float* sw, int E) {
    int i = blockIdx.x * blockDim.x + threadIdx.x;
    if (i < E) {
        int d = dst[i];
        int pos = rowptr[d] + atomicAdd(&fill[d], 1);
        ssrc[pos] = src[i];
        sw[pos]   = w[i];
    }
}

// ---------------- sparse aggregation: Y[d] = sum_e w_e * X[src_e] ----------------
// one warp per destination vertex; lane covers cols [lane*4, lane*4+3] and
// [128+lane*2, 128+lane*2+1] via one float4 + one float2 gather per edge.
__global__ __launch_bounds__(256) void k_agg(const float* __restrict__ X,
                                             float* __restrict__ Y,
                                             const int* __restrict__ rowptr,
                                             const int* __restrict__ ssrc,
                                             const float* __restrict__ sw, int M) {
    int warp = (blockIdx.x * blockDim.x + threadIdx.x) >> 5;
    int lane = threadIdx.x & 31;
    if (warp >= M) return;
    int beg = rowptr[warp], end = rowptr[warp + 1];
    float4 a4 = make_float4(0.f, 0.f, 0.f, 0.f);
    float2 a2 = make_float2(0.f, 0.f);
#pragma unroll 2
    for (int e = beg; e < end; e++) {
        int   s  = __ldg(ssrc + e);
        float wt = __ldg(sw + e);
        const float* r = X + (size_t)s * H;
        float4 v4 = __ldg((const float4*)r + lane);
        float2 v2 = __ldg((const float2*)(r + 128) + lane);
        a4.x += wt * v4.x;
        a4.y += wt * v4.y;
        a4.z += wt * v4.z;
        a4.w += wt * v4.w;
        a2.x += wt * v2.x;
        a2.y += wt * v2.y;
    }
    float* o = Y + (size_t)warp * H;
    ((float4*)o)[lane] = a4;
    ((float2*)(o + 128))[lane] = a2;
}

// ---------------- tf32 tensor-core GEMM + fused epilogue -------------------------
// C = A[M,192] @ W[192,192];  out = relu(C + bias)                (mode 0)
//                             out = (res + relu(C + bias)) * 0.5  (mode 1)
// block: 64 rows x 192 cols, 256 threads (8 warps).
// warp tile: 32 rows x 48 cols = 2 (m16) x 6 (n8) mma tiles, K chunked by 32.
#define SA 36    // A smem row stride (floats): bank = gid*4+tig -> conflict-free frags
#define SB 200   // B smem row stride (floats): bank = tig*8+gid -> conflict-free frags

__device__ __forceinline__ unsigned f2tf32(float x) {
    unsigned u;
    asm("cvt.rna.tf32.f32 %0, %1;" : "=r"(u) : "f"(x));
    return u;
}

__device__ __forceinline__ void mma_tf32(float* c, const unsigned* a,
                                         unsigned b0, unsigned b1) {
    asm volatile(
        "mma.sync.aligned.m16n8k8.row.col.f32.tf32.tf32.f32 "
        "{%0,%1,%2,%3}, {%4,%5,%6,%7}, {%8,%9}, {%0,%1,%2,%3};"
        : "+f"(c[0]), "+f"(c[1]), "+f"(c[2]), "+f"(c[3])
        : "r"(a[0]), "r"(a[1]), "r"(a[2]), "r"(a[3]), "r"(b0), "r"(b1));
}

__global__ __launch_bounds__(256) void k_gemm_tf32(const float* __restrict__ A,
                                                   const float* __restrict__ Wm,
                                                   const float* __restrict__ bias,
                                                   const float* __restrict__ res,
                                                   float* __restrict__ out,
                                                   int M, int mode) {
    __shared__ unsigned As[BM * SA];   // [row][k] 64 x 32 (+pad), tf32 bits
    __shared__ unsigned Bs[32 * SB];   // [k][n]   32 x 192 (+pad), tf32 bits

    int tid  = threadIdx.x;
    int lane = tid & 31;
    int warp = tid >> 5;
    int gid  = lane >> 2;    // 0..7
    int tig  = lane & 3;     // 0..3
    int rowg = warp & 1;     // warp row group: 32 rows each
    int colg = warp >> 1;    // warp col group: 48 cols each
    int m0   = blockIdx.x * BM;

    float c[2][6][4];
#pragma unroll
    for (int t = 0; t < 2; t++)
#pragma unroll
        for (int j = 0; j < 6; j++)
#pragma unroll
            for (int q = 0; q < 4; q++) c[t][j][q] = 0.f;

    // A loader mapping: 64x32 floats = 2 float4 per thread
    int arow = tid >> 2;
    int akk  = (tid & 3) * 8;

    for (int it = 0; it < 6; it++) {
        int k0 = it * 32;
        __syncthreads();   // previous compute done before overwrite
        // ---- stage A chunk ----
        {
            int gr = m0 + arow;
            float4 v0 = make_float4(0.f, 0.f, 0.f, 0.f);
            float4 v1 = v0;
            if (gr < M) {
                const float* p = A + (size_t)gr * H + k0 + akk;
                v0 = *(const float4*)p;
                v1 = *(const float4*)(p + 4);
            }
            unsigned* d = &As[arow * SA + akk];
            d[0] = f2tf32(v0.x); d[1] = f2tf32(v0.y);
            d[2] = f2tf32(v0.z); d[3] = f2tf32(v0.w);
            d[4] = f2tf32(v1.x); d[5] = f2tf32(v1.y);
            d[6] = f2tf32(v1.z); d[7] = f2tf32(v1.w);
        }
        // ---- stage B chunk: 32x192 floats = 6 float4 per thread ----
#pragma unroll
        for (int i = 0; i < 6; i++) {
            int f4  = tid + 256 * i;
            int row = f4 / 48;
            int cc  = (f4 % 48) * 4;
            float4 w = *(const float4*)(Wm + (size_t)(k0 + row) * H + cc);
            unsigned* d = &Bs[row * SB + cc];
            d[0] = f2tf32(w.x); d[1] = f2tf32(w.y);
            d[2] = f2tf32(w.z); d[3] = f2tf32(w.w);
        }
        __syncthreads();
        // ---- compute 4 k8-steps ----
#pragma unroll
        for (int ks = 0; ks < 4; ks++) {
            int kk = ks * 8;
            unsigned a[2][4];
#pragma unroll
            for (int t = 0; t < 2; t++) {
                int r = rowg * 32 + t * 16 + gid;
                a[t][0] = As[r * SA + kk + tig];
                a[t][1] = As[(r + 8) * SA + kk + tig];
                a[t][2] = As[r * SA + kk + tig + 4];
                a[t][3] = As[(r + 8) * SA + kk + tig + 4];
            }
#pragma unroll
            for (int j = 0; j < 6; j++) {
                int n = colg * 48 + j * 8 + gid;
                unsigned b0 = Bs[(kk + tig) * SB + n];
                unsigned b1 = Bs[(kk + tig + 4) * SB + n];
                mma_tf32(c[0][j], a[0], b0, b1);
                mma_tf32(c[1][j], a[1], b0, b1);
            }
        }
    }

    // ---- epilogue: bias + relu (+ residual average) ----
    float2 bb[6];
#pragma unroll
    for (int j = 0; j < 6; j++)
        bb[j] = *(const float2*)(bias + colg * 48 + j * 8 + tig * 2);

#pragma unroll
    for (int t = 0; t < 2; t++) {
#pragma unroll
        for (int h = 0; h < 2; h++) {
            int m = m0 + rowg * 32 + t * 16 + gid + h * 8;
            if (m < M) {
                float* orow = out + (size_t)m * H + colg * 48 + tig * 2;
                const float* rrow = res + (size_t)m * H + colg * 48 + tig * 2;
#pragma unroll
                for (int j = 0; j < 6; j++) {
                    float v0 = fmaxf(c[t][j][h * 2 + 0] + bb[j].x, 0.f);
                    float v1 = fmaxf(c[t][j][h * 2 + 1] + bb[j].y, 0.f);
                    if (mode == 1) {
                        float2 r2 = *(const float2*)(rrow + j * 8);
                        v0 = (r2.x + v0) * 0.5f;
                        v1 = (r2.y + v1) * 0.5f;
                    }
                    float2 o2; o2.x = v0; o2.y = v1;
                    *(float2*)(orow + j * 8) = o2;
                }
            }
        }
    }
}

// ---------------- output head: coords = Y @ W_out + b_out (192 -> 3) -------------
__global__ __launch_bounds__(256) void k_head(const float* __restrict__ Y,
                                              const float* __restrict__ Wout,
                                              const float* __restrict__ bout,
                                              float* __restrict__ out, int M) {
    int warp = (blockIdx.x * blockDim.x + threadIdx.x) >> 5;
    int lane = threadIdx.x & 31;
    if (warp >= M) return;
    const float* y = Y + (size_t)warp * H;
    float a0 = 0.f, a1 = 0.f, a2 = 0.f;
#pragma unroll
    for (int k0 = 0; k0 < H; k0 += 32) {
        float v = __ldg(y + k0 + lane);
        const float* wr = Wout + (size_t)(k0 + lane) * 3;
        a0 += v * __ldg(wr + 0);
        a1 += v * __ldg(wr + 1);
        a2 += v * __ldg(wr + 2);
    }
#pragma unroll
    for (int off = 16; off; off >>= 1) {
        a0 += __shfl_down_sync(0xffffffffu, a0, off);
        a1 += __shfl_down_sync(0xffffffffu, a1, off);
        a2 += __shfl_down_sync(0xffffffffu, a2, off);
    }
    if (lane == 0) {
        out[(size_t)warp * 3 + 0] = a0 + __ldg(bout + 0);
        out[(size_t)warp * 3 + 1] = a1 + __ldg(bout + 1);
        out[(size_t)warp * 3 + 2] = a2 + __ldg(bout + 2);
    }
}

__global__ void k_copy4(const float* __restrict__ src, float* __restrict__ dst, int n4) {
    int i = blockIdx.x * blockDim.x + threadIdx.x;
    if (i < n4) ((float4*)dst)[i] = ((const float4*)src)[i];
}

// ---------------- launch ---------------------------------------------------------
extern "C" void kernel_launch(void* const* d_in, const int* in_sizes, int n_in,
                              void* d_out, int out_size) {
    const float* features = (const float*)d_in[0];
    const int*   esrc     = (const int*)d_in[1];
    const int*   edst     = (const int*)d_in[2];
    const float* ew       = (const float*)d_in[3];
    const float* Ws       = (const float*)d_in[4];
    const float* bs       = (const float*)d_in[5];
    const float* Wout     = (const float*)d_in[6];
    const float* bout     = (const float*)d_in[7];
    float* out = (float*)d_out;

    int M = in_sizes[0] / H;   // 25000
    int E = in_sizes[1];       // 400000

    float *Y, *X, *F, *sw;
    int *rp, *cnt, *fill, *ssrc;
    cudaGetSymbolAddress((void**)&Y, g_Y);
    cudaGetSymbolAddress((void**)&X, g_X);
    cudaGetSymbolAddress((void**)&F, g_F);
    cudaGetSymbolAddress((void**)&sw, g_sw);
    cudaGetSymbolAddress((void**)&rp, g_rowptr);
    cudaGetSymbolAddress((void**)&cnt, g_cnt);
    cudaGetSymbolAddress((void**)&fill, g_fill);
    cudaGetSymbolAddress((void**)&ssrc, g_ssrc);

    // ---- CSR build (by destination) ----
    k_zero2<<<(M + 255) / 256, 256>>>(cnt, fill, M);
    k_hist<<<(E + 255) / 256, 256>>>(edst, cnt, E);
    k_scan<<<1, 1024>>>(cnt, rp, M);
    k_scatter<<<(E + 255) / 256, 256>>>(esrc, edst, ew, rp, fill, ssrc, sw, E);

    int aggGrid  = (M * 32 + 255) / 256;
    int gemmGrid = (M + BM - 1) / BM;

    // layer 0: x = relu(gcn(features))
    k_agg<<<aggGrid, 256>>>(features, Y, rp, ssrc, sw, M);
    k_gemm_tf32<<<gemmGrid, 256>>>(Y, Ws, bs, features /*unused*/, X, M, 0);
    // layer 1: feats = (features + relu(gcn(x))) / 2
    k_agg<<<aggGrid, 256>>>(X, Y, rp, ssrc, sw, M);
    k_gemm_tf32<<<gemmGrid, 256>>>(Y, Ws + (size_t)1 * H * H, bs + 1 * H, features, F, M, 1);

    // blocks: layers (2,3) (4,5) (6,7) (8,9) (10,11)
    for (int l = 2; l < 12; l += 2) {
        k_agg<<<aggGrid, 256>>>(F, Y, rp, ssrc, sw, M);
        k_gemm_tf32<<<gemmGrid, 256>>>(Y, Ws + (size_t)l * H * H, bs + (size_t)l * H, F /*unused*/, X, M, 0);
        k_agg<<<aggGrid, 256>>>(X, Y, rp, ssrc, sw, M);
        k_gemm_tf32<<<gemmGrid, 256>>>(Y, Ws + (size_t)(l + 1) * H * H, bs + (size_t)(l + 1) * H, F, F, M, 1);
    }

    // gc13: feats = (feats + relu(gcn(feats))) / 2
    k_agg<<<aggGrid, 256>>>(F, Y, rp, ssrc, sw, M);
    k_gemm_tf32<<<gemmGrid, 256>>>(Y, Ws + (size_t)12 * H * H, bs + (size_t)12 * H, F, F, M, 1);

    // head: coords = gcn(feats) with W_out/b_out (no relu)
    k_agg<<<aggGrid, 256>>>(F, Y, rp, ssrc, sw, M);
    k_head<<<(M * 32 + 255) / 256, 256>>>(Y, Wout, bout, out, M);

    // second output: feats, appended after coords
    if (out_size >= M * 3 + M * H) {
        k_copy4<<<((M * H) / 4 + 255) / 256, 256>>>(F, out + (size_t)M * 3, (M * H) / 4);
    }
}